// round 15
// baseline (speedup 1.0000x reference)
#include <cuda_runtime.h>
#include <cuda_fp16.h>
#include <cstdint>
#include <math.h>

// ----------------------------------------------------------------------------
// LorentzLinear R15: barrier-free mainloop.
//  - cvtW kernel precomputes per-lane B mma fragments: builds the old swizzled
//    stage image in ITS OWN smem, runs the proven ldmatrix sequence, stores
//    frags to g_wf[j][wn][ks][g][lane] (uint4). Self-calibrating layout.
//  - main kernel: CTA = 64 rows x 512 cols (256 thr, warps 2 wm x 4 wn,
//    warp tile m32n64), A panel resident in smem, B fragments via coalesced
//    LDG.128 from g_wf (L1-cached). NO syncthreads / cp.async in the 32-iter
//    mainloop. 2 CTAs/SM. Fused Lorentz epilogue as R11.
// ----------------------------------------------------------------------------

#define THREADS 256
#define BM      64
#define KD      512
#define ND      512
#define NTOT    32          // 2 chunks x 16 k-tiles
#define NROWS   65536

// B fragments: 32 tiles x (4 wn x 2 ks x 4 g x 32 lanes) uint4 = 512KB
__device__ uint4 g_wf[32 * 1024];

// main-kernel smem (bytes)
#define OFF_APAN 0
#define APAN_SZ  (64 * 1024)
#define OFF_PART APAN_SZ
#define OFF_Y0T  (OFF_PART + 256)
#define SMEM_TOTAL (OFF_Y0T + 256)       // 65.5 KB -> 2 CTAs/SM easily

__device__ __forceinline__ uint32_t smem_u32(const void* p) {
    uint32_t a;
    asm("{ .reg .u64 t; cvta.to.shared.u64 t, %1; cvt.u32.u64 %0, t; }"
        : "=r"(a) : "l"(p));
    return a;
}

__device__ __forceinline__ void ldm4(uint32_t r[4], uint32_t addr) {
    asm volatile("ldmatrix.sync.aligned.m8n8.x4.shared.b16 {%0,%1,%2,%3}, [%4];"
                 : "=r"(r[0]), "=r"(r[1]), "=r"(r[2]), "=r"(r[3]) : "r"(addr));
}

__device__ __forceinline__ void mma16816(float c[4], const uint32_t a[4],
                                         uint32_t b0, uint32_t b1) {
    asm volatile(
        "mma.sync.aligned.m16n8k16.row.col.f32.f16.f16.f32 "
        "{%0,%1,%2,%3}, {%4,%5,%6,%7}, {%8,%9}, {%0,%1,%2,%3};"
        : "+f"(c[0]), "+f"(c[1]), "+f"(c[2]), "+f"(c[3])
        : "r"(a[0]), "r"(a[1]), "r"(a[2]), "r"(a[3]), "r"(b0), "r"(b1));
}

__device__ __forceinline__ void sts128(uint32_t addr, uint32_t r0, uint32_t r1,
                                       uint32_t r2, uint32_t r3) {
    asm volatile("st.shared.v4.b32 [%0], {%1,%2,%3,%4};"
                 :: "r"(addr), "r"(r0), "r"(r1), "r"(r2), "r"(r3) : "memory");
}

// ---------------- kernel A: W -> fragment-ordered fp16 images ---------------
// One CTA per k-tile j (32 CTAs, 128 threads = 4 warps, warp w = wn).
// Step 1: build the 16KB swizzled stage image (same mapping as R11's cvtW)
//         in smem. Step 2: run R11's exact ldmatrix address sequence and
//         store the resulting fragments to g_wf.

__global__ void __launch_bounds__(128)
cvtW_kernel(const float* __restrict__ W) {
    __shared__ uint4 stg[1024];          // 16KB stage image
    const int tid  = threadIdx.x;
    const int lane = tid & 31;
    const int wn   = tid >> 5;           // 0..3
    const uint32_t j = blockIdx.x;       // tile 0..31 (chunk = j>>4, kt = j&15)

    // ---- fill stage image (1024 units, 8 per thread) ----
    #pragma unroll
    for (int i = 0; i < 8; ++i) {
        const uint32_t u   = tid + i * 128;
        const uint32_t off = u << 4;
        const uint32_t jj  = off >> 12;
        const uint32_t q   = off & 4095;
        const uint32_t p   = q >> 7;
        const uint32_t swz = (q >> 4) & 7;
        const uint32_t cu6 = swz ^ (p & 7);
        const uint32_t wrow = (j >> 4) * 256 + jj * 64 + p * 2 + (cu6 >> 2);
        const uint32_t k0   = (j & 15) * 32 + (cu6 & 3) * 8;
        const float* src = W + (size_t)wrow * KD + k0;
        float4 v0 = *reinterpret_cast<const float4*>(src);
        float4 v1 = *reinterpret_cast<const float4*>(src + 4);
        __half2 h[4];
        h[0] = __floats2half2_rn(v0.x, v0.y);
        h[1] = __floats2half2_rn(v0.z, v0.w);
        h[2] = __floats2half2_rn(v1.x, v1.y);
        h[3] = __floats2half2_rn(v1.z, v1.w);
        stg[u] = *reinterpret_cast<uint4*>(h);
    }
    __syncthreads();

    // ---- run the proven ldmatrix sequence, dump frags ----
    const uint32_t sbase = smem_u32(stg);
    const int l15 = lane & 15;
    const int hi  = lane >> 4;
    const uint32_t bBase = sbase + (wn * 32 + (l15 >> 1)) * 128;
    const uint32_t kbm   = (l15 >> 1) & 7;
    const uint32_t bhb   = (l15 & 1) * 4;
    #pragma unroll
    for (int ks = 0; ks < 2; ++ks) {
        const uint32_t bxo = (((bhb + 2 * ks + hi) ^ kbm) << 4);
        #pragma unroll
        for (int g = 0; g < 4; ++g) {
            uint32_t bb[4];
            ldm4(bb, bBase + g * 1024 + bxo);
            g_wf[j * 1024 + wn * 256 + ks * 128 + g * 32 + lane] =
                make_uint4(bb[0], bb[1], bb[2], bb[3]);
        }
    }
}

// ---------------- main kernel ----------------

__global__ void __launch_bounds__(THREADS, 2)
lorentz_kernel(const float* __restrict__ x, const float* __restrict__ bias,
               const float* __restrict__ scale, float* __restrict__ out) {
    extern __shared__ char smem[];
    const uint32_t sb = smem_u32(smem);
    const int tid  = threadIdx.x;
    const int lane = tid & 31;
    const int w    = tid >> 5;          // 0..7
    const int wm   = w >> 2;            // 0..1 (32 rows each)
    const int wn   = w & 3;             // 0..3 (64 cols each)
    const int l15  = lane & 15;
    const int hi   = lane >> 4;
    const int row0 = blockIdx.x * BM;

    float* part = (float*)(smem + OFF_PART);   // [64] ssq -> r
    float* y0t  = (float*)(smem + OFF_Y0T);    // [64] y0 -> t

    if (tid < 64) part[tid] = 0.f;

    // ---- A panel: convert 64x512 f32 -> fp16 smem (4096 units, 16/thread) --
    #pragma unroll
    for (int i = 0; i < 16; ++i) {
        const int u   = tid + i * THREADS;
        const int row = u >> 6, cu = u & 63;
        const float* src = x + (size_t)(row0 + row) * KD + cu * 8;
        float4 v0 = *reinterpret_cast<const float4*>(src);
        float4 v1 = *reinterpret_cast<const float4*>(src + 4);
        __half2 h0 = __floats2half2_rn(v0.x, v0.y);
        __half2 h1 = __floats2half2_rn(v0.z, v0.w);
        __half2 h2 = __floats2half2_rn(v1.x, v1.y);
        __half2 h3 = __floats2half2_rn(v1.z, v1.w);
        const uint32_t dst = sb + OFF_APAN + row * 1024 + ((cu ^ (row & 7)) << 4);
        sts128(dst, *(uint32_t*)&h0, *(uint32_t*)&h1,
                    *(uint32_t*)&h2, *(uint32_t*)&h3);
    }
    __syncthreads();     // the ONLY pre-epilogue barrier

    // ---- addressing ----
    const uint32_t aRow  = wm * 32 + l15;
    const uint32_t aBase = sb + OFF_APAN + aRow * 1024;
    const uint32_t ka    = aRow & 7;
    const uint4* __restrict__ bP = g_wf + wn * 256 + lane;

    float acc[2][8][4];
    #pragma unroll
    for (int m = 0; m < 2; ++m)
        #pragma unroll
        for (int f = 0; f < 8; ++f)
            #pragma unroll
            for (int k = 0; k < 4; ++k) acc[m][f][k] = 0.f;

    // ---- barrier-free mainloop: 32 k-tile iterations over both N-chunks ----
    #pragma unroll 1
    for (int j = 0; j < NTOT; ++j) {
        // B fragments (coalesced 512B/warp LDG.128; L1-cached, wm-pair reuse)
        uint4 b0 = __ldg(bP + 0);
        uint4 b1 = __ldg(bP + 32);
        uint4 b2 = __ldg(bP + 64);
        uint4 b3 = __ldg(bP + 96);
        uint4 b4 = __ldg(bP + 128);
        uint4 b5 = __ldg(bP + 160);
        uint4 b6 = __ldg(bP + 192);
        uint4 b7 = __ldg(bP + 224);
        bP += 1024;

        const uint32_t u0 = (uint32_t)((j & 15) * 4 + hi);
        uint32_t a0[4], a1[4];

        // ks = 0
        {
            const uint32_t axo = ((u0 ^ ka) << 4);
            ldm4(a0, aBase + axo);
            ldm4(a1, aBase + 16 * 1024 + axo);
            mma16816(acc[0][0], a0, b0.x, b0.z);
            mma16816(acc[0][1], a0, b0.y, b0.w);
            mma16816(acc[1][0], a1, b0.x, b0.z);
            mma16816(acc[1][1], a1, b0.y, b0.w);
            mma16816(acc[0][2], a0, b1.x, b1.z);
            mma16816(acc[0][3], a0, b1.y, b1.w);
            mma16816(acc[1][2], a1, b1.x, b1.z);
            mma16816(acc[1][3], a1, b1.y, b1.w);
            mma16816(acc[0][4], a0, b2.x, b2.z);
            mma16816(acc[0][5], a0, b2.y, b2.w);
            mma16816(acc[1][4], a1, b2.x, b2.z);
            mma16816(acc[1][5], a1, b2.y, b2.w);
            mma16816(acc[0][6], a0, b3.x, b3.z);
            mma16816(acc[0][7], a0, b3.y, b3.w);
            mma16816(acc[1][6], a1, b3.x, b3.z);
            mma16816(acc[1][7], a1, b3.y, b3.w);
        }
        // ks = 1
        {
            const uint32_t axo = (((u0 + 2) ^ ka) << 4);
            ldm4(a0, aBase + axo);
            ldm4(a1, aBase + 16 * 1024 + axo);
            mma16816(acc[0][0], a0, b4.x, b4.z);
            mma16816(acc[0][1], a0, b4.y, b4.w);
            mma16816(acc[1][0], a1, b4.x, b4.z);
            mma16816(acc[1][1], a1, b4.y, b4.w);
            mma16816(acc[0][2], a0, b5.x, b5.z);
            mma16816(acc[0][3], a0, b5.y, b5.w);
            mma16816(acc[1][2], a1, b5.x, b5.z);
            mma16816(acc[1][3], a1, b5.y, b5.w);
            mma16816(acc[0][4], a0, b6.x, b6.z);
            mma16816(acc[0][5], a0, b6.y, b6.w);
            mma16816(acc[1][4], a1, b6.x, b6.z);
            mma16816(acc[1][5], a1, b6.y, b6.w);
            mma16816(acc[0][6], a0, b7.x, b7.z);
            mma16816(acc[0][7], a0, b7.y, b7.w);
            mma16816(acc[1][6], a1, b7.x, b7.z);
            mma16816(acc[1][7], a1, b7.y, b7.w);
        }

        if (j == 15) {
            // ---- chunk-0 epilogue (cols 0..255): bias, ssq, stash, reset ----
            float p[2][2] = {{0.f, 0.f}, {0.f, 0.f}};
            #pragma unroll
            for (int m = 0; m < 2; ++m) {
                #pragma unroll
                for (int f = 0; f < 8; ++f) {
                    const int col = wn * 64 + f * 8 + (lane & 3) * 2;
                    const float2 bv = __ldg(reinterpret_cast<const float2*>(bias + col));
                    acc[m][f][0] += bv.x; acc[m][f][1] += bv.y;
                    acc[m][f][2] += bv.x; acc[m][f][3] += bv.y;
                    p[m][0] += acc[m][f][0] * acc[m][f][0] + acc[m][f][1] * acc[m][f][1];
                    p[m][1] += acc[m][f][2] * acc[m][f][2] + acc[m][f][3] * acc[m][f][3];
                }
            }
            if (wn == 0 && (lane & 3) == 0) {
                #pragma unroll
                for (int m = 0; m < 2; ++m) {
                    p[m][0] -= acc[m][0][0] * acc[m][0][0];
                    p[m][1] -= acc[m][0][2] * acc[m][0][2];
                    y0t[wm * 32 + m * 16 + (lane >> 2)]     = acc[m][0][0];
                    y0t[wm * 32 + m * 16 + 8 + (lane >> 2)] = acc[m][0][2];
                }
            }
            #pragma unroll
            for (int m = 0; m < 2; ++m)
                #pragma unroll
                for (int h = 0; h < 2; ++h) {
                    float v = p[m][h];
                    v += __shfl_xor_sync(0xffffffffu, v, 1);
                    v += __shfl_xor_sync(0xffffffffu, v, 2);
                    if ((lane & 3) == 0)
                        atomicAdd(&part[wm * 32 + m * 16 + h * 8 + (lane >> 2)], v);
                }
            #pragma unroll
            for (int m = 0; m < 2; ++m) {
                const int rlo = wm * 32 + m * 16 + (lane >> 2);
                #pragma unroll
                for (int f = 0; f < 8; ++f) {
                    const int c = wn * 64 + f * 8 + (lane & 3) * 2;
                    *reinterpret_cast<float2*>(out + (size_t)(row0 + rlo) * ND + c) =
                        make_float2(acc[m][f][0], acc[m][f][1]);
                    *reinterpret_cast<float2*>(out + (size_t)(row0 + rlo + 8) * ND + c) =
                        make_float2(acc[m][f][2], acc[m][f][3]);
                }
            }
            #pragma unroll
            for (int m = 0; m < 2; ++m)
                #pragma unroll
                for (int f = 0; f < 8; ++f)
                    #pragma unroll
                    for (int k = 0; k < 4; ++k) acc[m][f][k] = 0.f;
        }
    }

    // ---- chunk-1 epilogue: bias + ssq ----
    {
        float p[2][2] = {{0.f, 0.f}, {0.f, 0.f}};
        #pragma unroll
        for (int m = 0; m < 2; ++m) {
            #pragma unroll
            for (int f = 0; f < 8; ++f) {
                const int col = 256 + wn * 64 + f * 8 + (lane & 3) * 2;
                const float2 bv = __ldg(reinterpret_cast<const float2*>(bias + col));
                acc[m][f][0] += bv.x; acc[m][f][1] += bv.y;
                acc[m][f][2] += bv.x; acc[m][f][3] += bv.y;
                p[m][0] += acc[m][f][0] * acc[m][f][0] + acc[m][f][1] * acc[m][f][1];
                p[m][1] += acc[m][f][2] * acc[m][f][2] + acc[m][f][3] * acc[m][f][3];
            }
        }
        #pragma unroll
        for (int m = 0; m < 2; ++m)
            #pragma unroll
            for (int h = 0; h < 2; ++h) {
                float v = p[m][h];
                v += __shfl_xor_sync(0xffffffffu, v, 1);
                v += __shfl_xor_sync(0xffffffffu, v, 2);
                if ((lane & 3) == 0)
                    atomicAdd(&part[wm * 32 + m * 16 + h * 8 + (lane >> 2)], v);
            }
    }
    __syncthreads();

    // ---- per-row scalars ----
    if (tid < 64) {
        const float tot = part[tid];
        const float y0 = y0t[tid];
        const float es = expf(scale[0]);
        const float t  = es / (1.f + expf(-y0)) + 1.1f;
        const float rr = sqrtf((t * t - 1.f) / fmaxf(tot, 1e-8f));
        part[tid] = rr;
        y0t[tid]  = t;
    }
    __syncthreads();

    // ---- write chunk 1 (cols 256..511) from registers, scaled ----
    #pragma unroll
    for (int m = 0; m < 2; ++m) {
        const int rlo = wm * 32 + m * 16 + (lane >> 2);
        const float rr0 = part[rlo], rr1 = part[rlo + 8];
        #pragma unroll
        for (int f = 0; f < 8; ++f) {
            const int c = 256 + wn * 64 + f * 8 + (lane & 3) * 2;
            *reinterpret_cast<float2*>(out + (size_t)(row0 + rlo) * ND + c) =
                make_float2(acc[m][f][0] * rr0, acc[m][f][1] * rr0);
            *reinterpret_cast<float2*>(out + (size_t)(row0 + rlo + 8) * ND + c) =
                make_float2(acc[m][f][2] * rr1, acc[m][f][3] * rr1);
        }
    }

    // ---- rescale chunk 0 (cols 0..255) in place (L2-hot) ----
    #pragma unroll 4
    for (int i = tid; i < 64 * 64; i += THREADS) {
        const int r  = i >> 6;
        const int c4 = (i & 63) * 4;
        const float rr = part[r];
        float* p4 = out + (size_t)(row0 + r) * ND + c4;
        float4 v = *reinterpret_cast<float4*>(p4);
        v.x *= rr; v.y *= rr; v.z *= rr; v.w *= rr;
        if (c4 == 0) v.x = y0t[r];
        *reinterpret_cast<float4*>(p4) = v;
    }
}

// ---------------- launch ----------------

extern "C" void kernel_launch(void* const* d_in, const int* in_sizes, int n_in,
                              void* d_out, int out_size) {
    const float* x     = (const float*)d_in[0];
    const float* W     = (const float*)d_in[1];
    const float* b     = (const float*)d_in[2];
    const float* scale = (const float*)d_in[3];
    float* out = (float*)d_out;

    cvtW_kernel<<<32, 128>>>(W);

    const int rows = in_sizes[0] / KD;     // 65536
    const int grid = rows / BM;            // 1024
    cudaFuncSetAttribute(lorentz_kernel,
                         cudaFuncAttributeMaxDynamicSharedMemorySize, SMEM_TOTAL);
    lorentz_kernel<<<grid, THREADS, SMEM_TOTAL>>>(x, b, scale, out);
}

// round 16
// speedup vs baseline: 1.1773x; 1.1773x over previous
#include <cuda_runtime.h>
#include <cuda_fp16.h>
#include <cstdint>
#include <math.h>

// ----------------------------------------------------------------------------
// LorentzLinear R16 = R11 with the mainloop __syncthreads replaced by
// per-pair named barriers.
//  - Warp-pair {wn, wn+4} (64 threads) produces AND consumes exactly block
//    [wn*4096,(wn+1)*4096) of each 16KB B stage -> pairwise sync suffices.
//  - bar.sync (1+wn), 64 per iteration; no full-CTA convoy in the mainloop.
//  - Rest identical to R11: 2 CTAs/SM, resident A panel, pre-tiled/swizzled
//    W scratch, 3-stage cp.async, fused Lorentz epilogue.
// ----------------------------------------------------------------------------

#define THREADS 256
#define BM      64
#define KD      512
#define ND      512
#define NTOT    32          // 2 chunks x 16 k-tiles
#define NST     3
#define NROWS   65536

// W scratch: 32 tiles x 16KB stage images, 16B units
__device__ uint4 g_wt[32 * 1024];

// smem layout (bytes)
#define OFF_APAN 0
#define APAN_SZ  (64 * 1024)
#define OFF_B    APAN_SZ
#define BST      16384
#define OFF_PART (OFF_B + NST * BST)
#define OFF_Y0T  (OFF_PART + 256)
#define SMEM_TOTAL (OFF_Y0T + 256)       // 115200 -> 2 CTAs = 230400

__device__ __forceinline__ uint32_t smem_u32(const void* p) {
    uint32_t a;
    asm("{ .reg .u64 t; cvta.to.shared.u64 t, %1; cvt.u32.u64 %0, t; }"
        : "=r"(a) : "l"(p));
    return a;
}

__device__ __forceinline__ void ldm4(uint32_t r[4], uint32_t addr) {
    asm volatile("ldmatrix.sync.aligned.m8n8.x4.shared.b16 {%0,%1,%2,%3}, [%4];"
                 : "=r"(r[0]), "=r"(r[1]), "=r"(r[2]), "=r"(r[3]) : "r"(addr));
}

__device__ __forceinline__ void mma16816(float c[4], const uint32_t a[4],
                                         uint32_t b0, uint32_t b1) {
    asm volatile(
        "mma.sync.aligned.m16n8k16.row.col.f32.f16.f16.f32 "
        "{%0,%1,%2,%3}, {%4,%5,%6,%7}, {%8,%9}, {%0,%1,%2,%3};"
        : "+f"(c[0]), "+f"(c[1]), "+f"(c[2]), "+f"(c[3])
        : "r"(a[0]), "r"(a[1]), "r"(a[2]), "r"(a[3]), "r"(b0), "r"(b1));
}

__device__ __forceinline__ void cp16(uint32_t smem_dst, const void* gsrc) {
    asm volatile("cp.async.cg.shared.global [%0], [%1], 16;"
                 :: "r"(smem_dst), "l"(gsrc));
}
#define CP_COMMIT() asm volatile("cp.async.commit_group;" ::: "memory")
#define CP_WAIT1()  asm volatile("cp.async.wait_group 1;" ::: "memory")

#define PAIR_BAR(id) asm volatile("bar.sync %0, 64;" :: "r"(id) : "memory")

__device__ __forceinline__ void sts128(uint32_t addr, uint32_t r0, uint32_t r1,
                                       uint32_t r2, uint32_t r3) {
    asm volatile("st.shared.v4.b32 [%0], {%1,%2,%3,%4};"
                 :: "r"(addr), "r"(r0), "r"(r1), "r"(r2), "r"(r3) : "memory");
}

// ---------------- kernel A: W f32 -> fp16, tiled+swizzled stage images ------

__global__ void __launch_bounds__(256)
cvtW_kernel(const float* __restrict__ W) {
    const uint32_t u = blockIdx.x * 256 + threadIdx.x;
    if (u >= 32 * 1024) return;
    const uint32_t j   = u >> 10;
    const uint32_t off = (u & 1023) << 4;
    const uint32_t jj  = off >> 12;
    const uint32_t q   = off & 4095;
    const uint32_t p   = q >> 7;
    const uint32_t swz = (q >> 4) & 7;
    const uint32_t cu6 = swz ^ (p & 7);
    const uint32_t wrow = (j >> 4) * 256 + jj * 64 + p * 2 + (cu6 >> 2);
    const uint32_t k0   = (j & 15) * 32 + (cu6 & 3) * 8;
    const float* src = W + (size_t)wrow * KD + k0;
    float4 v0 = *reinterpret_cast<const float4*>(src);
    float4 v1 = *reinterpret_cast<const float4*>(src + 4);
    __half2 h[4];
    h[0] = __floats2half2_rn(v0.x, v0.y);
    h[1] = __floats2half2_rn(v0.z, v0.w);
    h[2] = __floats2half2_rn(v1.x, v1.y);
    h[3] = __floats2half2_rn(v1.z, v1.w);
    g_wt[u] = *reinterpret_cast<uint4*>(h);
}

// ---------------- main kernel ----------------

__global__ void __launch_bounds__(THREADS, 2)
lorentz_kernel(const float* __restrict__ x, const float* __restrict__ bias,
               const float* __restrict__ scale, float* __restrict__ out) {
    extern __shared__ char smem[];
    const uint32_t sb = smem_u32(smem);
    const int tid  = threadIdx.x;
    const int lane = tid & 31;
    const int w    = tid >> 5;          // 0..7
    const int wm   = w >> 2;            // 0..1 (32 rows each)
    const int wn   = w & 3;             // 0..3 (64 cols each)
    const int l15  = lane & 15;
    const int hi   = lane >> 4;
    const int row0 = blockIdx.x * BM;
    const int barid = 1 + wn;           // named barrier per pair {wn, wn+4}

    float* part = (float*)(smem + OFF_PART);   // [64] ssq -> r
    float* y0t  = (float*)(smem + OFF_Y0T);    // [64] y0 -> t

    if (tid < 64) part[tid] = 0.f;

    // ---- pair-block B copy: pair wn copies units [wn*256, wn*256+256) ----
    // in-pair thread index pt = wm*32 + lane; 4 units per thread.
    const uint32_t pt    = (uint32_t)(wm * 32 + lane);
    const uint32_t ubase = (uint32_t)(wn * 256) + pt;
    const uint32_t bDstU = sb + OFF_B + ubase * 16;

    #define ISSUE(J) do {                                                     \
        const int _j = (J);                                                   \
        if (_j < NTOT) {                                                      \
            const int _st = _j % NST;                                         \
            const uint4* _src = g_wt + _j * 1024 + ubase;                     \
            const uint32_t _d = bDstU + _st * BST;                            \
            cp16(_d,            _src);                                        \
            cp16(_d + 64 * 16,  _src + 64);                                   \
            cp16(_d + 128 * 16, _src + 128);                                  \
            cp16(_d + 192 * 16, _src + 192);                                  \
        }                                                                     \
        CP_COMMIT();                                                          \
    } while (0)

    ISSUE(0);
    ISSUE(1);

    // ---- A panel: convert 64x512 f32 -> fp16 smem (4096 units, 16/thread) --
    #pragma unroll
    for (int i = 0; i < 16; ++i) {
        const int u   = tid + i * THREADS;
        const int row = u >> 6, cu = u & 63;
        const float* src = x + (size_t)(row0 + row) * KD + cu * 8;
        float4 v0 = *reinterpret_cast<const float4*>(src);
        float4 v1 = *reinterpret_cast<const float4*>(src + 4);
        __half2 h0 = __floats2half2_rn(v0.x, v0.y);
        __half2 h1 = __floats2half2_rn(v0.z, v0.w);
        __half2 h2 = __floats2half2_rn(v1.x, v1.y);
        __half2 h3 = __floats2half2_rn(v1.z, v1.w);
        const uint32_t dst = sb + OFF_APAN + row * 1024 + ((cu ^ (row & 7)) << 4);
        sts128(dst, *(uint32_t*)&h0, *(uint32_t*)&h1,
                    *(uint32_t*)&h2, *(uint32_t*)&h3);
    }
    __syncthreads();   // A panel + part[] visible to all

    // ---- ldmatrix addressing (identical to R11) ----
    const uint32_t aRow  = wm * 32 + l15;
    const uint32_t aBase = sb + OFF_APAN + aRow * 1024;
    const uint32_t ka    = aRow & 7;
    const uint32_t bBase = sb + OFF_B + (wn * 32 + (l15 >> 1)) * 128;
    const uint32_t kbm   = (l15 >> 1) & 7;
    const uint32_t bhb   = (l15 & 1) * 4;
    const uint32_t bxo0  = (((bhb + 0 + hi) ^ kbm) << 4);
    const uint32_t bxo1  = (((bhb + 2 + hi) ^ kbm) << 4);

    float acc[2][8][4];
    #pragma unroll
    for (int m = 0; m < 2; ++m)
        #pragma unroll
        for (int f = 0; f < 8; ++f)
            #pragma unroll
            for (int k = 0; k < 4; ++k) acc[m][f][k] = 0.f;

    // ---- flat mainloop: 32 iterations, pair-local synchronization only ----
    #pragma unroll 1
    for (int j = 0; j < NTOT; ++j) {
        const int st = j % NST;
        CP_WAIT1();          // own copies for stage st have landed
        PAIR_BAR(barid);     // partner warp's copies landed + its j-1 reads done
        ISSUE(j + 2);        // safe: stage (j+2)%NST was consumed at j-1

        const uint32_t bS = bBase + st * BST;
        const uint32_t u0 = (uint32_t)((j & 15) * 4 + hi);
        #pragma unroll
        for (int ks = 0; ks < 2; ++ks) {
            const uint32_t axo = (((u0 + 2 * ks) ^ ka) << 4);
            uint32_t a0[4], a1[4];
            ldm4(a0, aBase + axo);
            ldm4(a1, aBase + 16 * 1024 + axo);
            const uint32_t bxo = ks ? bxo1 : bxo0;
            #pragma unroll
            for (int g = 0; g < 4; ++g) {
                uint32_t bb[4];
                ldm4(bb, bS + g * 1024 + bxo);
                mma16816(acc[0][2 * g],     a0, bb[0], bb[2]);
                mma16816(acc[0][2 * g + 1], a0, bb[1], bb[3]);
                mma16816(acc[1][2 * g],     a1, bb[0], bb[2]);
                mma16816(acc[1][2 * g + 1], a1, bb[1], bb[3]);
            }
        }

        if (j == 15) {
            // ---- chunk-0 epilogue (cols 0..255): bias, ssq, stash, reset ----
            float p[2][2] = {{0.f, 0.f}, {0.f, 0.f}};
            #pragma unroll
            for (int m = 0; m < 2; ++m) {
                #pragma unroll
                for (int f = 0; f < 8; ++f) {
                    const int col = wn * 64 + f * 8 + (lane & 3) * 2;
                    const float2 bv = __ldg(reinterpret_cast<const float2*>(bias + col));
                    acc[m][f][0] += bv.x; acc[m][f][1] += bv.y;
                    acc[m][f][2] += bv.x; acc[m][f][3] += bv.y;
                    p[m][0] += acc[m][f][0] * acc[m][f][0] + acc[m][f][1] * acc[m][f][1];
                    p[m][1] += acc[m][f][2] * acc[m][f][2] + acc[m][f][3] * acc[m][f][3];
                }
            }
            if (wn == 0 && (lane & 3) == 0) {
                #pragma unroll
                for (int m = 0; m < 2; ++m) {
                    p[m][0] -= acc[m][0][0] * acc[m][0][0];
                    p[m][1] -= acc[m][0][2] * acc[m][0][2];
                    y0t[wm * 32 + m * 16 + (lane >> 2)]     = acc[m][0][0];
                    y0t[wm * 32 + m * 16 + 8 + (lane >> 2)] = acc[m][0][2];
                }
            }
            #pragma unroll
            for (int m = 0; m < 2; ++m)
                #pragma unroll
                for (int h = 0; h < 2; ++h) {
                    float v = p[m][h];
                    v += __shfl_xor_sync(0xffffffffu, v, 1);
                    v += __shfl_xor_sync(0xffffffffu, v, 2);
                    if ((lane & 3) == 0)
                        atomicAdd(&part[wm * 32 + m * 16 + h * 8 + (lane >> 2)], v);
                }
            #pragma unroll
            for (int m = 0; m < 2; ++m) {
                const int rlo = wm * 32 + m * 16 + (lane >> 2);
                #pragma unroll
                for (int f = 0; f < 8; ++f) {
                    const int c = wn * 64 + f * 8 + (lane & 3) * 2;
                    *reinterpret_cast<float2*>(out + (size_t)(row0 + rlo) * ND + c) =
                        make_float2(acc[m][f][0], acc[m][f][1]);
                    *reinterpret_cast<float2*>(out + (size_t)(row0 + rlo + 8) * ND + c) =
                        make_float2(acc[m][f][2], acc[m][f][3]);
                }
            }
            #pragma unroll
            for (int m = 0; m < 2; ++m)
                #pragma unroll
                for (int f = 0; f < 8; ++f)
                    #pragma unroll
                    for (int k = 0; k < 4; ++k) acc[m][f][k] = 0.f;
        }
    }
    #undef ISSUE

    // ---- chunk-1 epilogue: bias + ssq ----
    {
        float p[2][2] = {{0.f, 0.f}, {0.f, 0.f}};
        #pragma unroll
        for (int m = 0; m < 2; ++m) {
            #pragma unroll
            for (int f = 0; f < 8; ++f) {
                const int col = 256 + wn * 64 + f * 8 + (lane & 3) * 2;
                const float2 bv = __ldg(reinterpret_cast<const float2*>(bias + col));
                acc[m][f][0] += bv.x; acc[m][f][1] += bv.y;
                acc[m][f][2] += bv.x; acc[m][f][3] += bv.y;
                p[m][0] += acc[m][f][0] * acc[m][f][0] + acc[m][f][1] * acc[m][f][1];
                p[m][1] += acc[m][f][2] * acc[m][f][2] + acc[m][f][3] * acc[m][f][3];
            }
        }
        #pragma unroll
        for (int m = 0; m < 2; ++m)
            #pragma unroll
            for (int h = 0; h < 2; ++h) {
                float v = p[m][h];
                v += __shfl_xor_sync(0xffffffffu, v, 1);
                v += __shfl_xor_sync(0xffffffffu, v, 2);
                if ((lane & 3) == 0)
                    atomicAdd(&part[wm * 32 + m * 16 + h * 8 + (lane >> 2)], v);
            }
    }
    __syncthreads();

    // ---- per-row scalars ----
    if (tid < 64) {
        const float tot = part[tid];
        const float y0 = y0t[tid];
        const float es = expf(scale[0]);
        const float t  = es / (1.f + expf(-y0)) + 1.1f;
        const float rr = sqrtf((t * t - 1.f) / fmaxf(tot, 1e-8f));
        part[tid] = rr;
        y0t[tid]  = t;
    }
    __syncthreads();

    // ---- write chunk 1 (cols 256..511) from registers, scaled ----
    #pragma unroll
    for (int m = 0; m < 2; ++m) {
        const int rlo = wm * 32 + m * 16 + (lane >> 2);
        const float rr0 = part[rlo], rr1 = part[rlo + 8];
        #pragma unroll
        for (int f = 0; f < 8; ++f) {
            const int c = 256 + wn * 64 + f * 8 + (lane & 3) * 2;
            *reinterpret_cast<float2*>(out + (size_t)(row0 + rlo) * ND + c) =
                make_float2(acc[m][f][0] * rr0, acc[m][f][1] * rr0);
            *reinterpret_cast<float2*>(out + (size_t)(row0 + rlo + 8) * ND + c) =
                make_float2(acc[m][f][2] * rr1, acc[m][f][3] * rr1);
        }
    }

    // ---- rescale chunk 0 (cols 0..255) in place (L2-hot) ----
    #pragma unroll 4
    for (int i = tid; i < 64 * 64; i += THREADS) {
        const int r  = i >> 6;
        const int c4 = (i & 63) * 4;
        const float rr = part[r];
        float* p4 = out + (size_t)(row0 + r) * ND + c4;
        float4 v = *reinterpret_cast<float4*>(p4);
        v.x *= rr; v.y *= rr; v.z *= rr; v.w *= rr;
        if (c4 == 0) v.x = y0t[r];
        *reinterpret_cast<float4*>(p4) = v;
    }
}

// ---------------- launch ----------------

extern "C" void kernel_launch(void* const* d_in, const int* in_sizes, int n_in,
                              void* d_out, int out_size) {
    const float* x     = (const float*)d_in[0];
    const float* W     = (const float*)d_in[1];
    const float* b     = (const float*)d_in[2];
    const float* scale = (const float*)d_in[3];
    float* out = (float*)d_out;

    cvtW_kernel<<<(32 * 1024 + 255) / 256, 256>>>(W);

    const int rows = in_sizes[0] / KD;     // 65536
    const int grid = rows / BM;            // 1024
    cudaFuncSetAttribute(lorentz_kernel,
                         cudaFuncAttributeMaxDynamicSharedMemorySize, SMEM_TOTAL);
    lorentz_kernel<<<grid, THREADS, SMEM_TOTAL>>>(x, b, scale, out);
}